// round 15
// baseline (speedup 1.0000x reference)
#include <cuda_runtime.h>
#include <cuda_fp16.h>
#include <cstdint>
#include <math.h>

#define BROWS 32768
#define DDIM  512
#define FDIM  512

#define BM 128
#define BN 128
#define BK 64
#define NKC (DDIM / BK)     // 8 k-chunks
#define STAGES 3
#define GTHREADS 256        // 8 warps, 2x4 grid, 64x32 warp tiles
#define NTILES (BROWS / BM) // 256 M-tile groups

// ---- scratch: x and W as fp16; monotonic generation flags (zero-init at load) ----
__device__ __half g_x[BROWS * DDIM];
__device__ __half g_w[FDIM * DDIM];
__device__ int    g_xflag[NTILES * 4];   // +1 per CTA per piece per launch (4 CTAs/piece)
__device__ int    g_wflag[4];            // +1 per launch (by bids 0..3)

// ---- SMEM layout (bytes, dynamic) ----
#define SM_STAGE0   1024
#define STAGE_BYTES 32768
#define T_A 0
#define T_B 16384
#define SMEM_TOTAL (SM_STAGE0 + STAGES * STAGE_BYTES)   // 99328 B -> 2 CTAs/SM

__device__ __forceinline__ uint32_t s2u(const void* p) {
    uint32_t a;
    asm("{ .reg .u64 t; cvta.to.shared.u64 t, %1; cvt.u32.u64 %0, t; }" : "=r"(a) : "l"(p));
    return a;
}

// 128B rows (64 fp16), 8-way XOR swizzle on 16B chunks (R7/R9-proven).
__device__ __forceinline__ uint32_t swz64(int row, int c16) {
    return (uint32_t)(row * 128 + ((c16 ^ (row & 7)) << 4));
}

__device__ __forceinline__ void cp_async16(uint32_t saddr, const void* gptr) {
    asm volatile("cp.async.cg.shared.global [%0], [%1], 16;" :: "r"(saddr), "l"(gptr));
}
#define CP_COMMIT() asm volatile("cp.async.commit_group;" ::: "memory")
#define CP_WAIT1()  asm volatile("cp.async.wait_group 1;" ::: "memory")

__device__ __forceinline__ void ldsm4(uint32_t addr, uint32_t* r) {
    asm volatile("ldmatrix.sync.aligned.m8n8.x4.shared.b16 {%0,%1,%2,%3}, [%4];"
                 : "=r"(r[0]), "=r"(r[1]), "=r"(r[2]), "=r"(r[3]) : "r"(addr));
}

__device__ __forceinline__ void mma_f16(float* c, const uint32_t* a, const uint32_t* b) {
    asm volatile(
        "mma.sync.aligned.m16n8k16.row.col.f32.f16.f16.f32 "
        "{%0,%1,%2,%3}, {%4,%5,%6,%7}, {%8,%9}, {%0,%1,%2,%3};"
        : "+f"(c[0]), "+f"(c[1]), "+f"(c[2]), "+f"(c[3])
        : "r"(a[0]), "r"(a[1]), "r"(a[2]), "r"(a[3]), "r"(b[0]), "r"(b[1]));
}

__device__ __forceinline__ uint32_t pack_h2(float x, float y) {
    __half h0 = __float2half_rn(x);
    __half h1 = __float2half_rn(y);
    return ((uint32_t)__half_as_ushort(h1) << 16) | __half_as_ushort(h0);
}

__device__ __forceinline__ void conv8(const float* __restrict__ src, size_t i8,
                                      __half* __restrict__ dst) {
    float4 v0 = reinterpret_cast<const float4*>(src)[i8 * 2];
    float4 v1 = reinterpret_cast<const float4*>(src)[i8 * 2 + 1];
    uint4 hp;
    hp.x = pack_h2(v0.x, v0.y);
    hp.y = pack_h2(v0.z, v0.w);
    hp.z = pack_h2(v1.x, v1.y);
    hp.w = pack_h2(v1.z, v1.w);
    reinterpret_cast<uint4*>(dst)[i8] = hp;
}

__device__ __forceinline__ int atom_add_release(int* p, int v) {
    int old;
    asm volatile("atom.global.add.release.gpu.s32 %0, [%1], %2;"
                 : "=r"(old) : "l"(p), "r"(v) : "memory");
    return old;
}

__device__ __forceinline__ int ld_acquire(const int* p) {
    int v;
    asm volatile("ld.global.acquire.gpu.b32 %0, [%1];" : "=r"(v) : "l"(p) : "memory");
    return v;
}

// ---------------- GEMM stage loader (R9, unchanged) ----------------
__device__ __forceinline__ void load_stage(uint32_t stage_base, int m0, int n0, int kc, int tid) {
#pragma unroll
    for (int q = tid; q < 1024; q += 256) {
        int r = q >> 3, c = q & 7;
        uint32_t soff = swz64(r, c);
        size_t gx = (size_t)(m0 + r) * DDIM + (size_t)kc * BK + c * 8;
        cp_async16(stage_base + T_A + soff, g_x + gx);
    }
#pragma unroll
    for (int q = tid; q < 1024; q += 256) {
        int r = q >> 3, c = q & 7;
        uint32_t soff = swz64(r, c);
        size_t gw = (size_t)(n0 + r) * DDIM + (size_t)kc * BK + c * 8;
        cp_async16(stage_base + T_B + soff, g_w + gw);
    }
}

__global__ void __launch_bounds__(GTHREADS, 2)
rank_activation_fused(const float* __restrict__ x, const float* __restrict__ W,
                      const float* __restrict__ av, const float* __restrict__ bv,
                      float* __restrict__ out) {
    extern __shared__ char smem[];
    uint32_t sm = s2u(smem);
    int tid = threadIdx.x;
    int bid = (int)blockIdx.x;
    int wid = tid >> 5;
    int l = tid & 31;
    int wm = wid >> 2;   // 0..1, 64 rows each
    int wn = wid & 3;    // 0..3, 32 cols each

    int mt  = bid >> 2;
    int sub = bid & 3;
    int m0 = mt * BM;
    int n0 = sub * BN;

    // a/b into smem early (overlaps conversion)
    if (tid < 128) {
        ((float*)smem)[tid]       = av[n0 + tid];
        ((float*)smem)[128 + tid] = bv[n0 + tid];
    }

    int gen = 0;   // generation, valid on tid==0 only

    // ---- W convert: group 0 only (bids 0..3, launched first). Quarter sub. ----
    if (mt == 0) {
        size_t base = (size_t)sub * 128 * DDIM / 8;   // 8192 conv8 units
#pragma unroll 4
        for (int q = tid; q < 8192; q += 256) conv8(W, base + q, g_w);
        __threadfence();
        __syncthreads();
        if (tid == 0) gen = atom_add_release(&g_wflag[sub], 1);
    }

    // ---- x convert: K-piece progressive, cooperative across the 4 group CTAs ----
    // piece p = cols [128p,128p+128); this CTA's share = rows [m0+32*sub, +32)
#pragma unroll
    for (int p = 0; p < 4; p++) {
#pragma unroll
        for (int q = tid; q < 512; q += 256) {
            int r = q >> 4, u = q & 15;   // 16 conv8 units per 128-col row segment
            size_t i8 = ((size_t)(m0 + 32 * sub + r) * DDIM + 128 * p) / 8 + u;
            conv8(x, i8, g_x);
        }
        __threadfence();
        __syncthreads();
        if (tid == 0) {
            int old = atom_add_release(&g_xflag[mt * 4 + p], 1);
            if (mt != 0 && p == 0) gen = old >> 2;   // 4 increments per piece per launch
        }
    }

    // ---- wait: piece 0 of my tile + my W quarter ----
    if (tid == 0) {
        int xt = 4 * (gen + 1);
        while (ld_acquire(&g_xflag[mt * 4 + 0]) < xt) __nanosleep(64);
        while (ld_acquire(&g_wflag[sub]) < gen + 1)   __nanosleep(64);
    }
    __syncthreads();

    // per-lane ldmatrix offsets: s = k16 step within BK=64 chunk (0..3)
    int g = l >> 3;
    uint32_t a_sw[4][4], b_sw[2][4];
#pragma unroll
    for (int mti = 0; mti < 4; mti++) {
        int row = wm * 64 + mti * 16 + ((g & 1) << 3) + (l & 7);
#pragma unroll
        for (int s = 0; s < 4; s++) a_sw[mti][s] = swz64(row, s * 2 + (g >> 1));
    }
#pragma unroll
    for (int t = 0; t < 2; t++) {
        int row = wn * 32 + t * 16 + ((g >> 1) << 3) + (l & 7);
#pragma unroll
        for (int s = 0; s < 4; s++) b_sw[t][s] = swz64(row, s * 2 + (g & 1));
    }

    float acc[4][4][4];
#pragma unroll
    for (int i = 0; i < 4; i++)
#pragma unroll
        for (int j = 0; j < 4; j++)
#pragma unroll
            for (int k = 0; k < 4; k++) acc[i][j][k] = 0.0f;

    // prologue: stages 0,1 (chunks 0,1 -> piece 0 only)
    load_stage(sm + SM_STAGE0, m0, n0, 0, tid);
    CP_COMMIT();
    load_stage(sm + SM_STAGE0 + STAGE_BYTES, m0, n0, 1, tid);
    CP_COMMIT();

    for (int kc = 0; kc < NKC; kc++) {
        // ensure the piece feeding chunk kc+2 has landed (tid0 spin, covered by barrier)
        if (tid == 0 && kc + 2 < NKC) {
            int p = (kc + 2) >> 1;
            int xt = 4 * (gen + 1);
            while (ld_acquire(&g_xflag[mt * 4 + p]) < xt) __nanosleep(64);
        }
        CP_WAIT1();
        __syncthreads();

        if (kc + 2 < NKC)
            load_stage(sm + SM_STAGE0 + ((kc + 2) % STAGES) * STAGE_BYTES, m0, n0, kc + 2, tid);
        CP_COMMIT();   // uniform group accounting

        uint32_t st = sm + SM_STAGE0 + (kc % STAGES) * STAGE_BYTES;
#pragma unroll
        for (int s = 0; s < 4; s++) {   // four k16 steps per 64-chunk
            uint32_t A[4][4], B[2][4];
#pragma unroll
            for (int t = 0; t < 2; t++) ldsm4(st + T_B + b_sw[t][s], B[t]);
#pragma unroll
            for (int mti = 0; mti < 4; mti++) ldsm4(st + T_A + a_sw[mti][s], A[mti]);
#pragma unroll
            for (int mti = 0; mti < 4; mti++) {
#pragma unroll
                for (int nt = 0; nt < 4; nt++) {
                    const uint32_t* bf = &B[nt >> 1][(nt & 1) * 2];
                    mma_f16(acc[mti][nt], A[mti], bf);
                }
            }
        }
    }

    // epilogue: out = tanh(a*z + b)
    const float* sA = (const float*)smem;
    const float* sB = (const float*)smem + 128;
#pragma unroll
    for (int mti = 0; mti < 4; mti++) {
        int row = m0 + wm * 64 + mti * 16 + (l >> 2);
#pragma unroll
        for (int nt = 0; nt < 4; nt++) {
            int cl = wn * 32 + nt * 8 + 2 * (l & 3);
            float a0 = sA[cl], a1 = sA[cl + 1];
            float b0 = sB[cl], b1 = sB[cl + 1];
            float2 v0, v1;
            v0.x = tanhf(fmaf(a0, acc[mti][nt][0], b0));
            v0.y = tanhf(fmaf(a1, acc[mti][nt][1], b1));
            v1.x = tanhf(fmaf(a0, acc[mti][nt][2], b0));
            v1.y = tanhf(fmaf(a1, acc[mti][nt][3], b1));
            *reinterpret_cast<float2*>(out + (size_t)row * FDIM + n0 + cl) = v0;
            *reinterpret_cast<float2*>(out + (size_t)(row + 8) * FDIM + n0 + cl) = v1;
        }
    }
}

extern "C" void kernel_launch(void* const* d_in, const int* in_sizes, int n_in,
                              void* d_out, int out_size) {
    const float* x = (const float*)d_in[0];
    const float* W = (const float*)d_in[1];
    const float* a = (const float*)d_in[2];
    const float* b = (const float*)d_in[3];
    float* out = (float*)d_out;

    cudaFuncSetAttribute(rank_activation_fused,
                         cudaFuncAttributeMaxDynamicSharedMemorySize, SMEM_TOTAL);
    dim3 grid((BROWS / BM) * (FDIM / BN));   // 1024
    rank_activation_fused<<<grid, GTHREADS, SMEM_TOTAL>>>(x, W, a, b, out);
}

// round 16
// speedup vs baseline: 1.2487x; 1.2487x over previous
#include <cuda_runtime.h>
#include <cuda_fp16.h>
#include <cstdint>
#include <math.h>

#define BROWS 32768
#define DDIM  512
#define FDIM  512

#define BM 128
#define BN 128
#define BK 64
#define NKC (DDIM / BK)     // 8 k-chunks
#define STAGES 3
#define GTHREADS 256        // 8 warps, 2x4 grid, 64x32 warp tiles
#define NTILES (BROWS / BM) // 256 M-tile groups

// ---- scratch: x and W as fp16; monotonic generation flags (zero-init at load) ----
__device__ __half g_x[BROWS * DDIM];
__device__ __half g_w[FDIM * DDIM];
__device__ int    g_flag[NTILES];   // +4 per tile per launch (x convert, 4 CTAs)
__device__ int    g_wflag[4];       // +8 per quarter per launch (W convert, 8 CTAs)

// ---- SMEM layout (bytes, dynamic) ----
#define SM_STAGE0   1024
#define STAGE_BYTES 32768
#define T_A 0
#define T_B 16384
#define SMEM_TOTAL (SM_STAGE0 + STAGES * STAGE_BYTES)   // 99328 B -> 2 CTAs/SM

__device__ __forceinline__ uint32_t s2u(const void* p) {
    uint32_t a;
    asm("{ .reg .u64 t; cvta.to.shared.u64 t, %1; cvt.u32.u64 %0, t; }" : "=r"(a) : "l"(p));
    return a;
}

// 128B rows (64 fp16), 8-way XOR swizzle on 16B chunks (R7/R9-proven).
__device__ __forceinline__ uint32_t swz64(int row, int c16) {
    return (uint32_t)(row * 128 + ((c16 ^ (row & 7)) << 4));
}

__device__ __forceinline__ void cp_async16(uint32_t saddr, const void* gptr) {
    asm volatile("cp.async.cg.shared.global [%0], [%1], 16;" :: "r"(saddr), "l"(gptr));
}
#define CP_COMMIT() asm volatile("cp.async.commit_group;" ::: "memory")
#define CP_WAIT1()  asm volatile("cp.async.wait_group 1;" ::: "memory")

__device__ __forceinline__ void ldsm4(uint32_t addr, uint32_t* r) {
    asm volatile("ldmatrix.sync.aligned.m8n8.x4.shared.b16 {%0,%1,%2,%3}, [%4];"
                 : "=r"(r[0]), "=r"(r[1]), "=r"(r[2]), "=r"(r[3]) : "r"(addr));
}

__device__ __forceinline__ void mma_f16(float* c, const uint32_t* a, const uint32_t* b) {
    asm volatile(
        "mma.sync.aligned.m16n8k16.row.col.f32.f16.f16.f32 "
        "{%0,%1,%2,%3}, {%4,%5,%6,%7}, {%8,%9}, {%0,%1,%2,%3};"
        : "+f"(c[0]), "+f"(c[1]), "+f"(c[2]), "+f"(c[3])
        : "r"(a[0]), "r"(a[1]), "r"(a[2]), "r"(a[3]), "r"(b[0]), "r"(b[1]));
}

__device__ __forceinline__ uint32_t pack_h2(float x, float y) {
    __half h0 = __float2half_rn(x);
    __half h1 = __float2half_rn(y);
    return ((uint32_t)__half_as_ushort(h1) << 16) | __half_as_ushort(h0);
}

__device__ __forceinline__ void conv8(const float* __restrict__ src, size_t i8,
                                      __half* __restrict__ dst) {
    float4 v0 = reinterpret_cast<const float4*>(src)[i8 * 2];
    float4 v1 = reinterpret_cast<const float4*>(src)[i8 * 2 + 1];
    uint4 hp;
    hp.x = pack_h2(v0.x, v0.y);
    hp.y = pack_h2(v0.z, v0.w);
    hp.z = pack_h2(v1.x, v1.y);
    hp.w = pack_h2(v1.z, v1.w);
    reinterpret_cast<uint4*>(dst)[i8] = hp;
}

__device__ __forceinline__ int atom_add_release(int* p, int v) {
    int old;
    asm volatile("atom.global.add.release.gpu.s32 %0, [%1], %2;"
                 : "=r"(old) : "l"(p), "r"(v) : "memory");
    return old;
}

__device__ __forceinline__ int ld_acquire(const int* p) {
    int v;
    asm volatile("ld.global.acquire.gpu.b32 %0, [%1];" : "=r"(v) : "l"(p) : "memory");
    return v;
}

// ---------------- GEMM stage loader (R9, unchanged) ----------------
__device__ __forceinline__ void load_stage(uint32_t stage_base, int m0, int n0, int kc, int tid) {
#pragma unroll
    for (int q = tid; q < 1024; q += 256) {
        int r = q >> 3, c = q & 7;
        uint32_t soff = swz64(r, c);
        size_t gx = (size_t)(m0 + r) * DDIM + (size_t)kc * BK + c * 8;
        cp_async16(stage_base + T_A + soff, g_x + gx);
    }
#pragma unroll
    for (int q = tid; q < 1024; q += 256) {
        int r = q >> 3, c = q & 7;
        uint32_t soff = swz64(r, c);
        size_t gw = (size_t)(n0 + r) * DDIM + (size_t)kc * BK + c * 8;
        cp_async16(stage_base + T_B + soff, g_w + gw);
    }
}

__global__ void __launch_bounds__(GTHREADS, 2)
rank_activation_fused(const float* __restrict__ x, const float* __restrict__ W,
                      const float* __restrict__ av, const float* __restrict__ bv,
                      float* __restrict__ out) {
    extern __shared__ char smem[];
    uint32_t sm = s2u(smem);
    int tid = threadIdx.x;
    int bid = (int)blockIdx.x;
    int wid = tid >> 5;
    int l = tid & 31;
    int wm = wid >> 2;   // 0..1, 64 rows each
    int wn = wid & 3;    // 0..3, 32 cols each

    int mt  = bid >> 2;
    int sub = bid & 3;
    int m0 = mt * BM;
    int n0 = sub * BN;

    // ---- W convert: 8 contributor CTAs per quarter (mt<8), 16 rows each, flagged FIRST ----
    if (mt < 8) {
        size_t base = ((size_t)(sub * 128 + mt * 16) * DDIM) / 8;   // 1024 conv8 units
#pragma unroll
        for (int q = tid; q < 1024; q += 256) conv8(W, base + q, g_w);
        __threadfence();
        __syncthreads();
        if (tid == 0) atom_add_release(&g_wflag[sub], 1);
    }

    // ---- Phase 1: convert this CTA's quarter of the x slab (32 contiguous rows) ----
    {
        size_t slab = (size_t)(m0 + sub * 32) * DDIM;   // contiguous 32x512 floats
        const float4* xs = reinterpret_cast<const float4*>(x + slab);
        uint4* xd = reinterpret_cast<uint4*>(g_x + slab);
#pragma unroll
        for (int q = tid; q < 2048; q += 256) {         // 2048 uint4 = 32KB fp16
            float4 v0 = xs[q * 2];
            float4 v1 = xs[q * 2 + 1];
            uint4 hp;
            hp.x = pack_h2(v0.x, v0.y);
            hp.y = pack_h2(v0.z, v0.w);
            hp.z = pack_h2(v1.x, v1.y);
            hp.w = pack_h2(v1.z, v1.w);
            xd[q] = hp;
        }
    }
    __threadfence();
    __syncthreads();

    // ---- Phase 2: generation-counter handshake (graph-replay safe, R13-proven) ----
    if (tid == 0) {
        int old = atom_add_release(&g_flag[mt], 1);
        int gen = old >> 2;                 // 4 increments per tile per launch
        int xt = (gen + 1) << 2;
        while (ld_acquire(&g_flag[mt]) < xt)            __nanosleep(64);
        while (ld_acquire(&g_wflag[sub]) < 8 * (gen + 1)) __nanosleep(64);
    }
    __syncthreads();

    if (tid < 128) {
        ((float*)smem)[tid]       = av[n0 + tid];
        ((float*)smem)[128 + tid] = bv[n0 + tid];
    }

    // per-lane ldmatrix offsets: s = k16 step within BK=64 chunk (0..3)
    int g = l >> 3;
    uint32_t a_sw[4][4], b_sw[2][4];
#pragma unroll
    for (int mti = 0; mti < 4; mti++) {
        int row = wm * 64 + mti * 16 + ((g & 1) << 3) + (l & 7);
#pragma unroll
        for (int s = 0; s < 4; s++) a_sw[mti][s] = swz64(row, s * 2 + (g >> 1));
    }
#pragma unroll
    for (int t = 0; t < 2; t++) {
        int row = wn * 32 + t * 16 + ((g >> 1) << 3) + (l & 7);
#pragma unroll
        for (int s = 0; s < 4; s++) b_sw[t][s] = swz64(row, s * 2 + (g & 1));
    }

    float acc[4][4][4];
#pragma unroll
    for (int i = 0; i < 4; i++)
#pragma unroll
        for (int j = 0; j < 4; j++)
#pragma unroll
            for (int k = 0; k < 4; k++) acc[i][j][k] = 0.0f;

    // prologue: stages 0,1
    load_stage(sm + SM_STAGE0, m0, n0, 0, tid);
    CP_COMMIT();
    load_stage(sm + SM_STAGE0 + STAGE_BYTES, m0, n0, 1, tid);
    CP_COMMIT();

    for (int kc = 0; kc < NKC; kc++) {
        CP_WAIT1();
        __syncthreads();

        if (kc + 2 < NKC)
            load_stage(sm + SM_STAGE0 + ((kc + 2) % STAGES) * STAGE_BYTES, m0, n0, kc + 2, tid);
        CP_COMMIT();   // uniform group accounting

        uint32_t st = sm + SM_STAGE0 + (kc % STAGES) * STAGE_BYTES;
#pragma unroll
        for (int s = 0; s < 4; s++) {   // four k16 steps per 64-chunk
            uint32_t A[4][4], B[2][4];
#pragma unroll
            for (int t = 0; t < 2; t++) ldsm4(st + T_B + b_sw[t][s], B[t]);
#pragma unroll
            for (int mti = 0; mti < 4; mti++) ldsm4(st + T_A + a_sw[mti][s], A[mti]);
#pragma unroll
            for (int mti = 0; mti < 4; mti++) {
#pragma unroll
                for (int nt = 0; nt < 4; nt++) {
                    const uint32_t* bf = &B[nt >> 1][(nt & 1) * 2];
                    mma_f16(acc[mti][nt], A[mti], bf);
                }
            }
        }
    }

    // epilogue: out = tanh(a*z + b)
    const float* sA = (const float*)smem;
    const float* sB = (const float*)smem + 128;
#pragma unroll
    for (int mti = 0; mti < 4; mti++) {
        int row = m0 + wm * 64 + mti * 16 + (l >> 2);
#pragma unroll
        for (int nt = 0; nt < 4; nt++) {
            int cl = wn * 32 + nt * 8 + 2 * (l & 3);
            float a0 = sA[cl], a1 = sA[cl + 1];
            float b0 = sB[cl], b1 = sB[cl + 1];
            float2 v0, v1;
            v0.x = tanhf(fmaf(a0, acc[mti][nt][0], b0));
            v0.y = tanhf(fmaf(a1, acc[mti][nt][1], b1));
            v1.x = tanhf(fmaf(a0, acc[mti][nt][2], b0));
            v1.y = tanhf(fmaf(a1, acc[mti][nt][3], b1));
            *reinterpret_cast<float2*>(out + (size_t)row * FDIM + n0 + cl) = v0;
            *reinterpret_cast<float2*>(out + (size_t)(row + 8) * FDIM + n0 + cl) = v1;
        }
    }
}

extern "C" void kernel_launch(void* const* d_in, const int* in_sizes, int n_in,
                              void* d_out, int out_size) {
    const float* x = (const float*)d_in[0];
    const float* W = (const float*)d_in[1];
    const float* a = (const float*)d_in[2];
    const float* b = (const float*)d_in[3];
    float* out = (float*)d_out;

    cudaFuncSetAttribute(rank_activation_fused,
                         cudaFuncAttributeMaxDynamicSharedMemorySize, SMEM_TOTAL);
    dim3 grid((BROWS / BM) * (FDIM / BN));   // 1024
    rank_activation_fused<<<grid, GTHREADS, SMEM_TOTAL>>>(x, W, a, b, out);
}